// round 2
// baseline (speedup 1.0000x reference)
#include <cuda_runtime.h>
#include <cuda_bf16.h>

// Two-stage deterministic reduction: sum(x) * a * b
// x: 8192*8192 fp32 (d_in[0]), a: scalar fp32 (d_in[1]), b: scalar fp32 (d_in[2])
// out: 1 fp32 scalar.

#define R1_BLOCKS 1184          // 148 SMs * 8 CTAs
#define R1_THREADS 256

__device__ float g_partials[R1_BLOCKS];

__global__ __launch_bounds__(R1_THREADS) void reduce_stage1(
    const float4* __restrict__ x4, long long n4)
{
    float s0 = 0.f, s1 = 0.f, s2 = 0.f, s3 = 0.f;
    long long idx    = (long long)blockIdx.x * blockDim.x + threadIdx.x;
    long long stride = (long long)gridDim.x * blockDim.x;

    // Grid-stride loop over float4s; 4 independent accumulator lanes keep the
    // FADD dependency chains short and let ptxas batch LDG.128s (MLP).
    #pragma unroll 4
    for (long long i = idx; i < n4; i += stride) {
        float4 v = x4[i];
        s0 += v.x; s1 += v.y; s2 += v.z; s3 += v.w;
    }
    float s = (s0 + s1) + (s2 + s3);

    // Warp reduce
    #pragma unroll
    for (int o = 16; o > 0; o >>= 1)
        s += __shfl_xor_sync(0xffffffffu, s, o);

    __shared__ float sh[R1_THREADS / 32];
    int lane = threadIdx.x & 31;
    int warp = threadIdx.x >> 5;
    if (lane == 0) sh[warp] = s;
    __syncthreads();

    if (warp == 0) {
        s = (lane < (R1_THREADS / 32)) ? sh[lane] : 0.f;
        #pragma unroll
        for (int o = 16; o > 0; o >>= 1)
            s += __shfl_xor_sync(0xffffffffu, s, o);
        if (lane == 0) g_partials[blockIdx.x] = s;
    }
}

__global__ __launch_bounds__(1024) void reduce_stage2(
    const float* __restrict__ a, const float* __restrict__ b,
    float* __restrict__ out, int nparts)
{
    float s = 0.f;
    for (int i = threadIdx.x; i < nparts; i += blockDim.x)
        s += g_partials[i];

    #pragma unroll
    for (int o = 16; o > 0; o >>= 1)
        s += __shfl_xor_sync(0xffffffffu, s, o);

    __shared__ float sh[32];
    int lane = threadIdx.x & 31;
    int warp = threadIdx.x >> 5;
    if (lane == 0) sh[warp] = s;
    __syncthreads();

    if (warp == 0) {
        s = (lane < 32) ? sh[lane] : 0.f;
        #pragma unroll
        for (int o = 16; o > 0; o >>= 1)
            s += __shfl_xor_sync(0xffffffffu, s, o);
        if (lane == 0)
            out[0] = s * a[0] * b[0];
    }
}

extern "C" void kernel_launch(void* const* d_in, const int* in_sizes, int n_in,
                              void* d_out, int out_size)
{
    const float* x = (const float*)d_in[0];
    const float* a = (const float*)d_in[1];
    const float* b = (const float*)d_in[2];
    float* out = (float*)d_out;

    long long n  = (long long)in_sizes[0];
    long long n4 = n >> 2;  // 8192*8192 divisible by 4

    reduce_stage1<<<R1_BLOCKS, R1_THREADS>>>((const float4*)x, n4);
    reduce_stage2<<<1, 1024>>>(a, b, out, R1_BLOCKS);
}